// round 1
// baseline (speedup 1.0000x reference)
#include <cuda_runtime.h>

// ---------------------------------------------------------------------------
// PConvLinear: out[b,n,o] = bias[o] + sum_f W[o,f] * pconv[b,n,f]
//   pconv[b,n, c*16+m] = sum_k feat[b,n,k,c] * wn[b,n,k,m]
//   feat[b,n,k,c] = c<64 ? x[b, nbr[b,n,k], c] : add[b,n,k,c-64]
// Shapes: B=2, N=60000, K=16, C=67, CM=16, F=1072, OUT=128
// ---------------------------------------------------------------------------

#define B_    2
#define N_    60000
#define K_    16
#define CIN_  64
#define F_    1072
#define OUT_  128
#define TP_   64       // points per block
#define THREADS_ 256
#define NCHUNK_ 17     // 17 * 64 f = 1088 (last chunk 48 valid f)
#define WSTRIDE_ 132   // padded o-stride for W_s rows
#define WNSTRIDE_ 65   // padded p-stride for wn_s

// smem layout (floats):
//   wn_s : 256 * 65  = 16640
//   W_s  : 64  * 132 = 8448
//   P_s  : 64  * 64  = 4096
//   g_s  : 16*4*64   = 4096
//   inds : 1024 ints (after the floats)
#define SMEM_FLOATS_ (16640 + 8448 + 4096 + 4096)
#define SMEM_BYTES_  (SMEM_FLOATS_ * 4 + 1024 * 4)

__device__ __forceinline__ unsigned long long pack2(float lo, float hi) {
    unsigned long long r;
    asm("mov.b64 %0, {%1, %2};" : "=l"(r) : "f"(lo), "f"(hi));
    return r;
}
__device__ __forceinline__ void unpack2(unsigned long long v, float& lo, float& hi) {
    asm("mov.b64 {%0, %1}, %2;" : "=f"(lo), "=f"(hi) : "l"(v));
}
__device__ __forceinline__ void fma2(unsigned long long& d,
                                     unsigned long long a,
                                     unsigned long long b) {
    asm("fma.rn.f32x2 %0, %1, %2, %0;" : "+l"(d) : "l"(a), "l"(b));
}

extern "C" __global__ void __launch_bounds__(THREADS_, 1)
pconv_linear_kernel(const float* __restrict__ xin,     // [B,N,64]
                    const int*   __restrict__ nbr,     // [B,N,16]
                    const float* __restrict__ wng,     // [B,N,16,16]
                    const float* __restrict__ addf,    // [B,N,16,3]
                    const float* __restrict__ W,       // [128,1072]
                    const float* __restrict__ bias,    // [128]
                    float*       __restrict__ out)     // [B,N,128]
{
    extern __shared__ float sm[];
    float* wn_s = sm;                      // 16640
    float* W_s  = wn_s + 16640;            // 8448
    float* P_s  = W_s + 8448;              // 4096
    float* g_s  = P_s + 4096;              // 4096
    int*   inds = (int*)(g_s + 4096);      // 1024 ints

    const int t    = threadIdx.x;
    const int base = blockIdx.x * TP_;

    // ---- load neighbor indices: 64 points x 16 (contiguous across block) ----
    {
        int lin = t * 4;
        *(int4*)&inds[lin] = *(const int4*)&nbr[(size_t)base * K_ + lin];
    }

    // ---- load weightnet into wn_s[k][m][p] (pad 65): 64 pts x 256 floats ----
    #pragma unroll
    for (int rep = 0; rep < 16; ++rep) {
        int lin = rep * 1024 + t * 4;            // 0..16383
        int p   = lin >> 8;                      // point within tile
        int r   = lin & 255;                     // k*16+m .. +3 (same k)
        float4 v = *(const float4*)&wng[(size_t)base * 256 + lin];
        wn_s[(r + 0) * WNSTRIDE_ + p] = v.x;
        wn_s[(r + 1) * WNSTRIDE_ + p] = v.y;
        wn_s[(r + 2) * WNSTRIDE_ + p] = v.z;
        wn_s[(r + 3) * WNSTRIDE_ + p] = v.w;
    }
    __syncthreads();

    // GEMM thread roles: outputs o in {tx*4..+3} U {64+tx*4..+3}, points ty*4..+3
    const int tx = t & 15;
    const int ty = t >> 4;
    // P-compute roles: point pP, m-quad mq
    const int pP = t & 63;
    const int mq = t >> 6;

    // bias into registers
    float bA[4], bB[4];
    #pragma unroll
    for (int j = 0; j < 4; ++j) {
        bA[j] = bias[tx * 4 + j];
        bB[j] = bias[64 + tx * 4 + j];
    }

    // accumulators: acc[pi][0..1] = o-pairs at tx*4, acc[pi][2..3] = at 64+tx*4
    unsigned long long acc[4][4];
    #pragma unroll
    for (int i = 0; i < 4; ++i)
        #pragma unroll
        for (int j = 0; j < 4; ++j) acc[i][j] = 0ULL;

    for (int cc = 0; cc < NCHUNK_; ++cc) {
        const int f0 = cc * 64;

        // ---- stage W chunk: W_s[f_local][o], zero-pad invalid f ----
        #pragma unroll
        for (int rep = 0; rep < 8; ++rep) {
            int lin = rep * 256 + t;             // 0..2047
            int o   = lin >> 4;
            int fq  = lin & 15;
            int f   = f0 + fq * 4;
            float4 v = make_float4(0.f, 0.f, 0.f, 0.f);
            if (f < F_) v = *(const float4*)&W[(size_t)o * F_ + f];
            W_s[(fq * 4 + 0) * WSTRIDE_ + o] = v.x;
            W_s[(fq * 4 + 1) * WSTRIDE_ + o] = v.y;
            W_s[(fq * 4 + 2) * WSTRIDE_ + o] = v.z;
            W_s[(fq * 4 + 3) * WSTRIDE_ + o] = v.w;
        }

        // ---- stage gathered features: g_s[k][c_local][p] ----
        #pragma unroll
        for (int rep = 0; rep < 4; ++rep) {
            int lin = rep * 256 + t;             // 0..1023
            int p   = lin & 63;
            int k   = lin >> 6;
            int pid = base + p;
            int b   = pid / N_;
            int n   = pid - b * N_;
            if (cc < 16) {
                int c0 = cc * 4;
                int nb = inds[p * 16 + k];
                float4 v = *(const float4*)&xin[((size_t)b * N_ + nb) * CIN_ + c0];
                g_s[(k * 4 + 0) * 64 + p] = v.x;
                g_s[(k * 4 + 1) * 64 + p] = v.y;
                g_s[(k * 4 + 2) * 64 + p] = v.z;
                g_s[(k * 4 + 3) * 64 + p] = v.w;
            } else {
                const float* a = &addf[((size_t)pid * K_ + k) * 3];
                g_s[(k * 4 + 0) * 64 + p] = a[0];
                g_s[(k * 4 + 1) * 64 + p] = a[1];
                g_s[(k * 4 + 2) * 64 + p] = a[2];
                g_s[(k * 4 + 3) * 64 + p] = 0.f;
            }
        }
        __syncthreads();

        // ---- compute P chunk: P_s[cl*16 + m][p] = sum_k g*wn ----
        {
            float pa[4][4];
            #pragma unroll
            for (int cl = 0; cl < 4; ++cl)
                #pragma unroll
                for (int j = 0; j < 4; ++j) pa[cl][j] = 0.f;

            #pragma unroll
            for (int k = 0; k < K_; ++k) {
                float w0 = wn_s[(k * 16 + mq * 4 + 0) * WNSTRIDE_ + pP];
                float w1 = wn_s[(k * 16 + mq * 4 + 1) * WNSTRIDE_ + pP];
                float w2 = wn_s[(k * 16 + mq * 4 + 2) * WNSTRIDE_ + pP];
                float w3 = wn_s[(k * 16 + mq * 4 + 3) * WNSTRIDE_ + pP];
                #pragma unroll
                for (int cl = 0; cl < 4; ++cl) {
                    float fv = g_s[(k * 4 + cl) * 64 + pP];
                    pa[cl][0] += fv * w0;
                    pa[cl][1] += fv * w1;
                    pa[cl][2] += fv * w2;
                    pa[cl][3] += fv * w3;
                }
            }
            #pragma unroll
            for (int cl = 0; cl < 4; ++cl)
                #pragma unroll
                for (int j = 0; j < 4; ++j)
                    P_s[(cl * 16 + mq * 4 + j) * 64 + pP] = pa[cl][j];
        }
        __syncthreads();

        // ---- GEMM: acc += P_chunk x W_chunk (packed f32x2 FFMA) ----
        #pragma unroll 8
        for (int fl = 0; fl < 64; ++fl) {
            float4 pv = *(const float4*)&P_s[fl * 64 + ty * 4];
            ulonglong2 wA = *(const ulonglong2*)&W_s[fl * WSTRIDE_ + tx * 4];
            ulonglong2 wB = *(const ulonglong2*)&W_s[fl * WSTRIDE_ + 64 + tx * 4];
            unsigned long long pp0 = pack2(pv.x, pv.x);
            unsigned long long pp1 = pack2(pv.y, pv.y);
            unsigned long long pp2 = pack2(pv.z, pv.z);
            unsigned long long pp3 = pack2(pv.w, pv.w);
            fma2(acc[0][0], pp0, wA.x); fma2(acc[0][1], pp0, wA.y);
            fma2(acc[0][2], pp0, wB.x); fma2(acc[0][3], pp0, wB.y);
            fma2(acc[1][0], pp1, wA.x); fma2(acc[1][1], pp1, wA.y);
            fma2(acc[1][2], pp1, wB.x); fma2(acc[1][3], pp1, wB.y);
            fma2(acc[2][0], pp2, wA.x); fma2(acc[2][1], pp2, wA.y);
            fma2(acc[2][2], pp2, wB.x); fma2(acc[2][3], pp2, wB.y);
            fma2(acc[3][0], pp3, wA.x); fma2(acc[3][1], pp3, wA.y);
            fma2(acc[3][2], pp3, wB.x); fma2(acc[3][3], pp3, wB.y);
        }
        __syncthreads();
    }

    // ---- epilogue: unpack, add bias, store ----
    #pragma unroll
    for (int pi = 0; pi < 4; ++pi) {
        int pid = base + ty * 4 + pi;
        float a0, a1, a2, a3, b0, b1, b2, b3;
        unpack2(acc[pi][0], a0, a1);
        unpack2(acc[pi][1], a2, a3);
        unpack2(acc[pi][2], b0, b1);
        unpack2(acc[pi][3], b2, b3);
        float4 rA = make_float4(a0 + bA[0], a1 + bA[1], a2 + bA[2], a3 + bA[3]);
        float4 rB = make_float4(b0 + bB[0], b1 + bB[1], b2 + bB[2], b3 + bB[3]);
        *(float4*)&out[(size_t)pid * OUT_ + tx * 4]      = rA;
        *(float4*)&out[(size_t)pid * OUT_ + 64 + tx * 4] = rB;
    }
}

extern "C" void kernel_launch(void* const* d_in, const int* in_sizes, int n_in,
                              void* d_out, int out_size) {
    const float* xin  = (const float*)d_in[0];
    const int*   nbr  = (const int*)d_in[1];
    const float* wng  = (const float*)d_in[2];
    const float* addf = (const float*)d_in[3];
    const float* W    = (const float*)d_in[4];
    const float* bias = (const float*)d_in[5];
    float*       out  = (float*)d_out;

    cudaFuncSetAttribute(pconv_linear_kernel,
                         cudaFuncAttributeMaxDynamicSharedMemorySize, SMEM_BYTES_);

    const int nblocks = (B_ * N_) / TP_;  // 120000 / 64 = 1875
    pconv_linear_kernel<<<nblocks, THREADS_, SMEM_BYTES_>>>(
        xin, nbr, wng, addf, W, bias, out);
}

// round 3
// speedup vs baseline: 1.3547x; 1.3547x over previous
#include <cuda_runtime.h>
#include <cstdint>

// ---------------------------------------------------------------------------
// PConvLinear via mma.sync tf32 (m16n8k8 HMMA), compute_103-safe.
//   out[p,o] = bias[o] + sum_f P[p,f] * W[o,f]
//   P[p, c*16+m] = sum_k feat[p,k,c] * wn[p,k,m]
// Per block: 128 points x 128 outputs. K processed as 2 k-halves x 34 chunks
// of 32 f (f padded 1072->1088); MMA accumulates across all 68 chunks.
// ---------------------------------------------------------------------------

#define NPTS 120000
#define NB   60000
#define TPB  128
#define THREADS 256
#define GRID ((NPTS + TPB - 1) / TPB)   // 938

#define TSTRIDE 36   // padded float stride of tf32 smem tiles (conflict-free)

// smem layout (float offsets)
#define OFF_WT   0        // 128 x 36  W tf32 tile [o][f]
#define OFF_PT   4608     // 128 x 36  P tf32 tile [p][f]
#define OFF_WN   9216     // 16384     wn k-half staging [k*16+m][p]
#define OFF_G    25600    // 8192      gathered feats [c_l*8+k][p]
#define OFF_I    33792    // 2048 ints neighbor inds
#define OFF_BIAS 35840    // 128
#define SMEM_BYTES (35968 * 4)   // 143,872 B

__device__ __forceinline__ uint32_t smem_u32(const void* p) {
    uint32_t a;
    asm("{ .reg .u64 t; cvta.to.shared.u64 t, %1; cvt.u32.u64 %0, t; }"
        : "=r"(a) : "l"(p));
    return a;
}
__device__ __forceinline__ uint32_t cvt_tf32(float f) {
    uint32_t r; asm("cvt.rna.tf32.f32 %0, %1;" : "=r"(r) : "f"(f)); return r;
}
__device__ __forceinline__ unsigned long long pack2(float lo, float hi) {
    unsigned long long r;
    asm("mov.b64 %0, {%1, %2};" : "=l"(r) : "f"(lo), "f"(hi));
    return r;
}
__device__ __forceinline__ void unpack2(unsigned long long v, float& lo, float& hi) {
    asm("mov.b64 {%0, %1}, %2;" : "=f"(lo), "=f"(hi) : "l"(v));
}
__device__ __forceinline__ void fma2(unsigned long long& d,
                                     unsigned long long a, unsigned long long b) {
    asm("fma.rn.f32x2 %0, %1, %2, %0;" : "+l"(d) : "l"(a), "l"(b));
}
__device__ __forceinline__ void ldsm4(uint32_t r[4], uint32_t addr) {
    asm volatile("ldmatrix.sync.aligned.m8n8.x4.shared.b16 {%0,%1,%2,%3}, [%4];"
                 : "=r"(r[0]), "=r"(r[1]), "=r"(r[2]), "=r"(r[3]) : "r"(addr));
}
__device__ __forceinline__ void mma8(float c[4], const uint32_t a[4],
                                     uint32_t b0, uint32_t b1) {
    asm volatile(
        "mma.sync.aligned.m16n8k8.row.col.f32.tf32.tf32.f32 "
        "{%0,%1,%2,%3}, {%4,%5,%6,%7}, {%8,%9}, {%0,%1,%2,%3};"
        : "+f"(c[0]), "+f"(c[1]), "+f"(c[2]), "+f"(c[3])
        : "r"(a[0]), "r"(a[1]), "r"(a[2]), "r"(a[3]), "r"(b0), "r"(b1));
}

extern "C" __global__ void __launch_bounds__(THREADS, 1)
pcl_kernel(const float* __restrict__ xin,   // [2,60000,64]
           const int*   __restrict__ nbr,   // [2,60000,16]
           const float* __restrict__ wng,   // [2,60000,16,16]
           const float* __restrict__ addf,  // [2,60000,16,3]
           const float* __restrict__ W,     // [128,1072]
           const float* __restrict__ bias,  // [128]
           float*       __restrict__ out)   // [2,60000,128]
{
    extern __shared__ __align__(16) float sm[];
    float* wns  = sm + OFF_WN;
    float* gs   = sm + OFF_G;
    int*   inds = (int*)(sm + OFF_I);

    const uint32_t smb = smem_u32(sm);
    const int t    = threadIdx.x;
    const int wid  = t >> 5;
    const int l    = t & 31;
    const int base = blockIdx.x * TPB;
    const int p    = t & 127;          // P-compute: point
    const int mh   = t >> 7;           // P-compute: m-half

    // MMA roles: warp grid 4(m) x 2(n)
    const int wm  = wid & 3;           // rows wm*32 .. +32
    const int wnb = wid >> 2;          // cols wnb*64 .. +64
    const uint32_t aBase = smb + (uint32_t)(OFF_PT + (wm * 32 + (l & 15)) * TSTRIDE
                                            + ((l & 16) ? 4 : 0)) * 4;
    const uint32_t bBase = smb + (uint32_t)(OFF_WT + (wnb * 64 + (l & 7)
                                            + ((l & 16) ? 8 : 0)) * TSTRIDE
                                            + ((l & 8) ? 4 : 0)) * 4;

    if (t < 128) sm[OFF_BIAS + t] = bias[t];

    // neighbor indices (guard last block)
    {
        int pt = base + (t >> 1);
        int4 z = make_int4(0, 0, 0, 0);
        int4 a = z, b = z;
        if (pt < NPTS) {
            const int4* s = (const int4*)(nbr + (size_t)pt * 16 + (size_t)(t & 1) * 8);
            a = s[0]; b = s[1];
        }
        ((int4*)inds)[t * 2 + 0] = a;
        ((int4*)inds)[t * 2 + 1] = b;
    }

    float acc[2][8][4];
    #pragma unroll
    for (int i = 0; i < 2; ++i)
        #pragma unroll
        for (int j = 0; j < 8; ++j)
            #pragma unroll
            for (int q = 0; q < 4; ++q) acc[i][j][q] = 0.f;

    unsigned long long wn2[8][4];
    const int ow = t >> 1;              // W staging: output row
    const int fh = (t & 1) * 16;        // W staging: f half

    for (int h = 0; h < 2; ++h) {
        // ---- stage wn k-half into smem [r=k*16+m][p] ----
        __syncthreads();
        #pragma unroll
        for (int rep = 0; rep < 16; ++rep) {
            int lin = rep * 1024 + t * 4;
            int pp  = lin >> 7;
            int r   = lin & 127;
            int pid = base + pp; if (pid > NPTS - 1) pid = NPTS - 1;
            float4 v = *(const float4*)(wng + (size_t)pid * 256 + h * 128 + r);
            wns[(r + 0) * 128 + pp] = v.x;
            wns[(r + 1) * 128 + pp] = v.y;
            wns[(r + 2) * 128 + pp] = v.z;
            wns[(r + 3) * 128 + pp] = v.w;
        }
        __syncthreads();
        // wn regs: f32x2 pairs for this thread's (p, m-half), 8 k
        #pragma unroll
        for (int k = 0; k < 8; ++k)
            #pragma unroll
            for (int j2 = 0; j2 < 4; ++j2) {
                float lo = wns[(k * 16 + mh * 8 + j2 * 2 + 0) * 128 + p];
                float hi = wns[(k * 16 + mh * 8 + j2 * 2 + 1) * 128 + p];
                wn2[k][j2] = pack2(lo, hi);
            }

        for (int gidx = 0; gidx < 9; ++gidx) {
            // ---- stage gathered features gs[(c_l*8+k)][p], 8 channels ----
            __syncthreads();
            #pragma unroll
            for (int rep = 0; rep < 4; ++rep) {
                int v  = rep * 256 + t;
                int pp = v & 127, kk = v >> 7;
                int pid  = base + pp;
                int pidc = pid > NPTS - 1 ? NPTS - 1 : pid;
                int kg = h * 8 + kk;
                if (gidx < 8) {
                    int cbase = gidx * 8;
                    int nb    = inds[pp * 16 + kg];
                    int brow  = (pidc >= NB) ? NB : 0;
                    const float4* src =
                        (const float4*)(xin + ((size_t)brow + nb) * 64 + cbase);
                    float4 a = src[0], b4 = src[1];
                    gs[(0 * 8 + kk) * 128 + pp] = a.x;
                    gs[(1 * 8 + kk) * 128 + pp] = a.y;
                    gs[(2 * 8 + kk) * 128 + pp] = a.z;
                    gs[(3 * 8 + kk) * 128 + pp] = a.w;
                    gs[(4 * 8 + kk) * 128 + pp] = b4.x;
                    gs[(5 * 8 + kk) * 128 + pp] = b4.y;
                    gs[(6 * 8 + kk) * 128 + pp] = b4.z;
                    gs[(7 * 8 + kk) * 128 + pp] = b4.w;
                } else {
                    const float* a = addf + ((size_t)pidc * 16 + kg) * 3;
                    gs[(0 * 8 + kk) * 128 + pp] = a[0];
                    gs[(1 * 8 + kk) * 128 + pp] = a[1];
                    gs[(2 * 8 + kk) * 128 + pp] = a[2];
                    #pragma unroll
                    for (int c = 3; c < 8; ++c) gs[(c * 8 + kk) * 128 + pp] = 0.f;
                }
            }
            __syncthreads();

            int ncl = (gidx < 8) ? 4 : 2;
            for (int cl2 = 0; cl2 < ncl; ++cl2) {
                // ---- W prefetch (LDG early; latency hides under P compute) ----
                int f0 = (gidx * 8 + cl2 * 2) * 16;
                float4 wv[4];
                #pragma unroll
                for (int j = 0; j < 4; ++j) {
                    int f = f0 + fh + j * 4;
                    wv[j] = (f < 1072)
                        ? *(const float4*)(W + (size_t)ow * 1072 + f)
                        : make_float4(0.f, 0.f, 0.f, 0.f);
                }

                // ---- P compute: 2 channels x 8 m from registers ----
                #pragma unroll
                for (int cl = 0; cl < 2; ++cl) {
                    int gb = ((cl2 * 2 + cl) * 8) * 128 + p;
                    unsigned long long a0 = 0, a1 = 0, a2 = 0, a3 = 0;
                    #pragma unroll
                    for (int k = 0; k < 8; ++k) {
                        float gv = gs[gb + k * 128];
                        unsigned long long g2 = pack2(gv, gv);
                        fma2(a0, g2, wn2[k][0]);
                        fma2(a1, g2, wn2[k][1]);
                        fma2(a2, g2, wn2[k][2]);
                        fma2(a3, g2, wn2[k][3]);
                    }
                    float v0, v1, v2, v3, v4, v5, v6, v7;
                    unpack2(a0, v0, v1); unpack2(a1, v2, v3);
                    unpack2(a2, v4, v5); unpack2(a3, v6, v7);
                    int fl = cl * 16 + mh * 8;
                    uint32_t* dst = (uint32_t*)(sm + OFF_PT + p * TSTRIDE + fl);
                    *(uint4*)(dst + 0) = make_uint4(cvt_tf32(v0), cvt_tf32(v1),
                                                    cvt_tf32(v2), cvt_tf32(v3));
                    *(uint4*)(dst + 4) = make_uint4(cvt_tf32(v4), cvt_tf32(v5),
                                                    cvt_tf32(v6), cvt_tf32(v7));
                }

                // ---- W convert + store [o][f] ----
                #pragma unroll
                for (int j = 0; j < 4; ++j) {
                    uint32_t* dst = (uint32_t*)(sm + OFF_WT + ow * TSTRIDE + fh + j * 4);
                    *(uint4*)dst = make_uint4(cvt_tf32(wv[j].x), cvt_tf32(wv[j].y),
                                              cvt_tf32(wv[j].z), cvt_tf32(wv[j].w));
                }
                __syncthreads();

                // ---- ldmatrix + 64 HMMA, accumulate in regs ----
                #pragma unroll
                for (int ks = 0; ks < 4; ++ks) {
                    uint32_t a0r[4], a1r[4];
                    ldsm4(a0r, aBase + ks * 32);
                    ldsm4(a1r, aBase + 16 * TSTRIDE * 4 + ks * 32);
                    #pragma unroll
                    for (int np = 0; np < 4; ++np) {
                        uint32_t b[4];
                        ldsm4(b, bBase + np * 16 * TSTRIDE * 4 + ks * 32);
                        mma8(acc[0][np * 2 + 0], a0r, b[0], b[1]);
                        mma8(acc[0][np * 2 + 1], a0r, b[2], b[3]);
                        mma8(acc[1][np * 2 + 0], a1r, b[0], b[1]);
                        mma8(acc[1][np * 2 + 1], a1r, b[2], b[3]);
                    }
                }
                __syncthreads();
            }
        }
    }

    // ---- epilogue: bias + store ----
    #pragma unroll
    for (int mt = 0; mt < 2; ++mt) {
        int r = wm * 32 + mt * 16 + (l >> 2);
        #pragma unroll
        for (int nt = 0; nt < 8; ++nt) {
            int o  = wnb * 64 + nt * 8 + 2 * (l & 3);
            float b0 = sm[OFF_BIAS + o], b1 = sm[OFF_BIAS + o + 1];
            int pid = base + r;
            if (pid < NPTS) {
                float2 v = make_float2(acc[mt][nt][0] + b0, acc[mt][nt][1] + b1);
                *(float2*)(out + (size_t)pid * 128 + o) = v;
            }
            int pid2 = base + r + 8;
            if (pid2 < NPTS) {
                float2 v = make_float2(acc[mt][nt][2] + b0, acc[mt][nt][3] + b1);
                *(float2*)(out + (size_t)pid2 * 128 + o) = v;
            }
        }
    }
}

extern "C" void kernel_launch(void* const* d_in, const int* in_sizes, int n_in,
                              void* d_out, int out_size) {
    const float* xin  = (const float*)d_in[0];
    const int*   nbr  = (const int*)d_in[1];
    const float* wng  = (const float*)d_in[2];
    const float* addf = (const float*)d_in[3];
    const float* W    = (const float*)d_in[4];
    const float* bias = (const float*)d_in[5];
    float*       out  = (float*)d_out;

    cudaFuncSetAttribute(pcl_kernel,
                         cudaFuncAttributeMaxDynamicSharedMemorySize, SMEM_BYTES);

    pcl_kernel<<<GRID, THREADS, SMEM_BYTES>>>(xin, nbr, wng, addf, W, bias, out);
}

// round 4
// speedup vs baseline: 2.0656x; 1.5247x over previous
#include <cuda_runtime.h>
#include <cstdint>

// ---------------------------------------------------------------------------
// PConvLinear via mma.sync tf32 (m16n8k8), single K pass (no k-half dup).
//   out[p,o] = bias[o] + sum_f P[p,f] * W[o,f]
//   P[p, c*16+m] = sum_{k<16} feat[p,k,c] * wn[p,k,m]
// Block: 512 threads, 128 points x 128 outputs, 34 chunks of 32 f.
// wn fully register-resident (4 threads/point, 4 m each, 16 k).
// Double-buffered tf32 tiles -> one __syncthreads per chunk.
// ---------------------------------------------------------------------------

#define NPTS 120000
#define NB   60000
#define TPB  128
#define THREADS 512
#define GRID ((NPTS + TPB - 1) / TPB)   // 938

#define TSTRIDE 36      // padded float stride of tf32 tiles (conflict-free)
#define TILE_FL (128 * TSTRIDE)   // 4608 floats per tile buffer

// smem layout (float offsets)
#define OFF_WT   0                      // 2 x 4608  W tf32 [o][f]
#define OFF_PT   (2 * TILE_FL)          // 2 x 4608  P tf32 [p][f]
#define OFF_G    (4 * TILE_FL)          // 16384     gathered feats [c8*16+k][p]
#define OFF_I    (4 * TILE_FL + 16384)  // 2048 ints neighbor inds
#define OFF_BIAS (OFF_I + 2048)         // 128
#define SMEM_FLOATS (OFF_BIAS + 128)
#define SMEM_BYTES (SMEM_FLOATS * 4)    // ~148 KB

__device__ __forceinline__ uint32_t smem_u32(const void* p) {
    uint32_t a;
    asm("{ .reg .u64 t; cvta.to.shared.u64 t, %1; cvt.u32.u64 %0, t; }"
        : "=r"(a) : "l"(p));
    return a;
}
__device__ __forceinline__ uint32_t cvt_tf32(float f) {
    uint32_t r; asm("cvt.rna.tf32.f32 %0, %1;" : "=r"(r) : "f"(f)); return r;
}
__device__ __forceinline__ unsigned long long pack2(float lo, float hi) {
    unsigned long long r;
    asm("mov.b64 %0, {%1, %2};" : "=l"(r) : "f"(lo), "f"(hi));
    return r;
}
__device__ __forceinline__ void unpack2(unsigned long long v, float& lo, float& hi) {
    asm("mov.b64 {%0, %1}, %2;" : "=f"(lo), "=f"(hi) : "l"(v));
}
__device__ __forceinline__ void fma2(unsigned long long& d,
                                     unsigned long long a, unsigned long long b) {
    asm("fma.rn.f32x2 %0, %1, %2, %0;" : "+l"(d) : "l"(a), "l"(b));
}
__device__ __forceinline__ void ldsm4(uint32_t r[4], uint32_t addr) {
    asm volatile("ldmatrix.sync.aligned.m8n8.x4.shared.b16 {%0,%1,%2,%3}, [%4];"
                 : "=r"(r[0]), "=r"(r[1]), "=r"(r[2]), "=r"(r[3]) : "r"(addr));
}
__device__ __forceinline__ void mma8(float c[4], const uint32_t a[4],
                                     uint32_t b0, uint32_t b1) {
    asm volatile(
        "mma.sync.aligned.m16n8k8.row.col.f32.tf32.tf32.f32 "
        "{%0,%1,%2,%3}, {%4,%5,%6,%7}, {%8,%9}, {%0,%1,%2,%3};"
        : "+f"(c[0]), "+f"(c[1]), "+f"(c[2]), "+f"(c[3])
        : "r"(a[0]), "r"(a[1]), "r"(a[2]), "r"(a[3]), "r"(b0), "r"(b1));
}

extern "C" __global__ void __launch_bounds__(THREADS, 1)
pcl_kernel(const float* __restrict__ xin,   // [2,60000,64]
           const int*   __restrict__ nbr,   // [2,60000,16]
           const float* __restrict__ wng,   // [2,60000,16,16]
           const float* __restrict__ addf,  // [2,60000,16,3]
           const float* __restrict__ W,     // [128,1072]
           const float* __restrict__ bias,  // [128]
           float*       __restrict__ out)   // [2,60000,128]
{
    extern __shared__ __align__(16) float sm[];
    float* gs   = sm + OFF_G;
    int*   inds = (int*)(sm + OFF_I);

    const uint32_t smb = smem_u32(sm);
    const int t    = threadIdx.x;
    const int wid  = t >> 5;
    const int l    = t & 31;
    const int base = blockIdx.x * TPB;
    const int p    = t & 127;          // P-compute: point
    const int mq   = t >> 7;           // P-compute: m-quad (4 m)

    // MMA roles: warp grid 4(m) x 4(n); each warp 32p x 32o
    const int wm  = wid & 3;
    const int wn  = wid >> 2;
    const uint32_t aBase = smb + (uint32_t)(OFF_PT + (wm * 32 + (l & 15)) * TSTRIDE
                                            + ((l & 16) ? 4 : 0)) * 4;
    const uint32_t bBase = smb + (uint32_t)(OFF_WT + (wn * 32 + (l & 7)
                                            + ((l & 16) ? 8 : 0)) * TSTRIDE
                                            + ((l & 8) ? 4 : 0)) * 4;

    if (t < 128) sm[OFF_BIAS + t] = bias[t];

    // ---- neighbor indices: 128 points x 16, int4 per thread ----
    {
        int pp = t >> 2;
        int pt = base + pp;
        int4 v = make_int4(0, 0, 0, 0);
        if (pt < NPTS)
            v = *(const int4*)(nbr + (size_t)pt * 16 + (size_t)(t & 3) * 4);
        ((int4*)inds)[t] = v;
    }

    // ---- stage wn (both halves) via gs region, load into registers ----
    unsigned long long wn2[16][2];
    #pragma unroll
    for (int h = 0; h < 2; ++h) {
        __syncthreads();
        #pragma unroll
        for (int rep = 0; rep < 8; ++rep) {
            int lin = rep * 2048 + t * 4;        // 0..16383
            int pp  = lin >> 7;
            int r   = lin & 127;                 // k_local*16 + m
            int pid = base + pp; if (pid > NPTS - 1) pid = NPTS - 1;
            float4 v = *(const float4*)(wng + (size_t)pid * 256 + h * 128 + r);
            gs[(r + 0) * 128 + pp] = v.x;
            gs[(r + 1) * 128 + pp] = v.y;
            gs[(r + 2) * 128 + pp] = v.z;
            gs[(r + 3) * 128 + pp] = v.w;
        }
        __syncthreads();
        #pragma unroll
        for (int k = 0; k < 8; ++k) {
            #pragma unroll
            for (int j2 = 0; j2 < 2; ++j2) {
                float lo = gs[(k * 16 + mq * 4 + j2 * 2 + 0) * 128 + p];
                float hi = gs[(k * 16 + mq * 4 + j2 * 2 + 1) * 128 + p];
                wn2[h * 8 + k][j2] = pack2(lo, hi);
            }
        }
    }

    float acc[2][4][4];
    #pragma unroll
    for (int i = 0; i < 2; ++i)
        #pragma unroll
        for (int j = 0; j < 4; ++j)
            #pragma unroll
            for (int q = 0; q < 4; ++q) acc[i][j][q] = 0.f;

    const int ow = t >> 2;              // W staging: output row
    const int fq = (t & 3) * 8;         // W staging: f offset (8 floats)

    int cg = 0;
    for (int gidx = 0; gidx < 9; ++gidx) {
        // ---- stage gathered feats gs[(c8*16+k)][p]: 8 ch x 16 k x 128 p ----
        __syncthreads();
        #pragma unroll
        for (int rep = 0; rep < 4; ++rep) {
            int v  = rep * 512 + t;             // 0..2047
            int pp = v & 127, kk = v >> 7;      // kk 0..15
            int pid  = base + pp;
            int pidc = pid > NPTS - 1 ? NPTS - 1 : pid;
            if (gidx < 8) {
                int cbase = gidx * 8;
                int nb    = inds[pp * 16 + kk];
                int brow  = (pidc >= NB) ? NB : 0;
                const float4* src =
                    (const float4*)(xin + ((size_t)brow + nb) * 64 + cbase);
                float4 a = src[0], b4 = src[1];
                gs[(0 * 16 + kk) * 128 + pp] = a.x;
                gs[(1 * 16 + kk) * 128 + pp] = a.y;
                gs[(2 * 16 + kk) * 128 + pp] = a.z;
                gs[(3 * 16 + kk) * 128 + pp] = a.w;
                gs[(4 * 16 + kk) * 128 + pp] = b4.x;
                gs[(5 * 16 + kk) * 128 + pp] = b4.y;
                gs[(6 * 16 + kk) * 128 + pp] = b4.z;
                gs[(7 * 16 + kk) * 128 + pp] = b4.w;
            } else {
                const float* a = addf + ((size_t)pidc * 16 + kk) * 3;
                gs[(0 * 16 + kk) * 128 + pp] = a[0];
                gs[(1 * 16 + kk) * 128 + pp] = a[1];
                gs[(2 * 16 + kk) * 128 + pp] = a[2];
                gs[(3 * 16 + kk) * 128 + pp] = 0.f;
            }
        }
        __syncthreads();

        const int ncl = (gidx < 8) ? 4 : 2;
        for (int cl2 = 0; cl2 < ncl; ++cl2, ++cg) {
            const int buf = cg & 1;
            float* Wb = sm + OFF_WT + buf * TILE_FL;
            float* Pb = sm + OFF_PT + buf * TILE_FL;
            const uint32_t bufoff = (uint32_t)(buf * TILE_FL) * 4;

            // ---- W prefetch (LDG, hides under P compute) ----
            const int f0 = (gidx * 8 + cl2 * 2) * 16;
            float4 wv[2];
            #pragma unroll
            for (int j = 0; j < 2; ++j) {
                int f = f0 + fq + j * 4;
                wv[j] = (f < 1072)
                    ? *(const float4*)(W + (size_t)ow * 1072 + f)
                    : make_float4(0.f, 0.f, 0.f, 0.f);
            }

            // ---- P compute: 2 channels x 4 m over 16 k (regs) ----
            #pragma unroll
            for (int cl = 0; cl < 2; ++cl) {
                int gb = ((cl2 * 2 + cl) * 16) * 128 + p;
                unsigned long long a0 = 0, a1 = 0;
                #pragma unroll
                for (int k = 0; k < 16; ++k) {
                    float gv = gs[gb + k * 128];
                    unsigned long long g2 = pack2(gv, gv);
                    fma2(a0, g2, wn2[k][0]);
                    fma2(a1, g2, wn2[k][1]);
                }
                float v0, v1, v2, v3;
                unpack2(a0, v0, v1); unpack2(a1, v2, v3);
                uint32_t* dst = (uint32_t*)(Pb + p * TSTRIDE + cl * 16 + mq * 4);
                *(uint4*)dst = make_uint4(cvt_tf32(v0), cvt_tf32(v1),
                                          cvt_tf32(v2), cvt_tf32(v3));
            }

            // ---- W convert + store [o][f] ----
            {
                uint32_t* dst = (uint32_t*)(Wb + ow * TSTRIDE + fq);
                *(uint4*)(dst + 0) = make_uint4(cvt_tf32(wv[0].x), cvt_tf32(wv[0].y),
                                                cvt_tf32(wv[0].z), cvt_tf32(wv[0].w));
                *(uint4*)(dst + 4) = make_uint4(cvt_tf32(wv[1].x), cvt_tf32(wv[1].y),
                                                cvt_tf32(wv[1].z), cvt_tf32(wv[1].w));
            }
            __syncthreads();

            // ---- ldmatrix + 32 HMMA per warp ----
            #pragma unroll
            for (int ks = 0; ks < 4; ++ks) {
                uint32_t a0r[4], a1r[4];
                ldsm4(a0r, aBase + bufoff + ks * 32);
                ldsm4(a1r, aBase + bufoff + 16 * TSTRIDE * 4 + ks * 32);
                #pragma unroll
                for (int np = 0; np < 2; ++np) {
                    uint32_t b[4];
                    ldsm4(b, bBase + bufoff + np * 16 * TSTRIDE * 4 + ks * 32);
                    mma8(acc[0][np * 2 + 0], a0r, b[0], b[1]);
                    mma8(acc[0][np * 2 + 1], a0r, b[2], b[3]);
                    mma8(acc[1][np * 2 + 0], a1r, b[0], b[1]);
                    mma8(acc[1][np * 2 + 1], a1r, b[2], b[3]);
                }
            }
            // no trailing sync: next chunk writes the other buffer; the next
            // chunk's sync orders MMA(c) before any write to this buffer (c+2).
        }
    }

    // ---- epilogue: bias + store (each warp 32p x 32o) ----
    #pragma unroll
    for (int mt = 0; mt < 2; ++mt) {
        int r = wm * 32 + mt * 16 + (l >> 2);
        #pragma unroll
        for (int nt = 0; nt < 4; ++nt) {
            int o  = wn * 32 + nt * 8 + 2 * (l & 3);
            float b0 = sm[OFF_BIAS + o], b1 = sm[OFF_BIAS + o + 1];
            int pid = base + r;
            if (pid < NPTS) {
                float2 v = make_float2(acc[mt][nt][0] + b0, acc[mt][nt][1] + b1);
                *(float2*)(out + (size_t)pid * 128 + o) = v;
            }
            int pid2 = base + r + 8;
            if (pid2 < NPTS) {
                float2 v = make_float2(acc[mt][nt][2] + b0, acc[mt][nt][3] + b1);
                *(float2*)(out + (size_t)pid2 * 128 + o) = v;
            }
        }
    }
}

extern "C" void kernel_launch(void* const* d_in, const int* in_sizes, int n_in,
                              void* d_out, int out_size) {
    const float* xin  = (const float*)d_in[0];
    const int*   nbr  = (const int*)d_in[1];
    const float* wng  = (const float*)d_in[2];
    const float* addf = (const float*)d_in[3];
    const float* W    = (const float*)d_in[4];
    const float* bias = (const float*)d_in[5];
    float*       out  = (float*)d_out;

    cudaFuncSetAttribute(pcl_kernel,
                         cudaFuncAttributeMaxDynamicSharedMemorySize, SMEM_BYTES);

    pcl_kernel<<<GRID, THREADS, SMEM_BYTES>>>(xin, nbr, wng, addf, W, bias, out);
}